// round 5
// baseline (speedup 1.0000x reference)
#include <cuda_runtime.h>
#include <cstdint>

#define Bn    16
#define NCn   80
#define An    33600
#define QAn   (An/4)          /* 8400 quads per frame */
#define FBLK  33              /* K1/K2 blocks per frame: 33*256 = 8448 >= 8400 */
#define PRE   750
#define POST  30
#define CH    256
#define HB    16384           /* bins: bits(1-s)>>16 <= 0x3F80 < 16384 */
#define CAP   1024

#define OUT_CLS_OFF  0
#define OUT_REG_OFF  (Bn*POST*CH)
#define OUT_BOX_OFF  (2*Bn*POST*CH)
#define OUT_SC_OFF   (2*Bn*POST*CH + Bn*POST*4)

__device__ float              g_maxs[Bn * An];
__device__ int                g_cls[Bn * An];
__device__ unsigned           g_hist[Bn * HB];   // zero at load; self-resetting
__device__ unsigned long long g_cand[Bn * CAP];
__device__ int                g_cnt[Bn];
__device__ int                g_thresh[Bn];
__device__ int                g_done[Bn];

static __device__ __forceinline__ unsigned score_bin(float s) {
    return __float_as_uint(1.0f - s) >> 16;   // bin ascending <=> score descending
}

// one warp-aggregated histogram add; d == 0xFFFFFFFF means "skip"
static __device__ __forceinline__ void agg_add(unsigned* H, unsigned d) {
    unsigned grp = __match_any_sync(0xFFFFFFFFu, d);
    if (d != 0xFFFFFFFFu) {
        if ((int)(threadIdx.x & 31) == (__ffs(grp) - 1))
            atomicAdd(&H[d], (unsigned)__popc(grp));
    }
}

// ---------------------------------------------------------------------------
// K1: max+argmax over 80 classes + warp-aggregated score histogram.
// Last block per frame (fence+ticket): pivot bin, zero hist, reset counters.
// ---------------------------------------------------------------------------
__global__ __launch_bounds__(256) void k_maxscore(const float* __restrict__ raw) {
    const int b = blockIdx.y;
    const int q = blockIdx.x * 256 + threadIdx.x;
    const bool valid = (q < QAn);
    const int qc = valid ? q : (QAn - 1);

    const float* base = raw + (size_t)b * 84 * An + (size_t)4 * An;

    float4 best = __ldg((const float4*)base + qc);
    int4 bi = make_int4(0, 0, 0, 0);
#pragma unroll 4
    for (int c = 1; c < NCn; ++c) {
        float4 v = __ldg((const float4*)(base + (size_t)c * An) + qc);
        if (v.x > best.x) { best.x = v.x; bi.x = c; }
        if (v.y > best.y) { best.y = v.y; bi.y = c; }
        if (v.z > best.z) { best.z = v.z; bi.z = c; }
        if (v.w > best.w) { best.w = v.w; bi.w = c; }
    }
    if (valid) {
        ((float4*)g_maxs)[b * QAn + q] = best;
        ((int4*)g_cls)[b * QAn + q] = bi;
    }

    unsigned* H = g_hist + (size_t)b * HB;
    agg_add(H, valid ? score_bin(best.x) : 0xFFFFFFFFu);
    agg_add(H, valid ? score_bin(best.y) : 0xFFFFFFFFu);
    agg_add(H, valid ? score_bin(best.z) : 0xFFFFFFFFu);
    agg_add(H, valid ? score_bin(best.w) : 0xFFFFFFFFu);

    // ---- fence + ticket: last block of this frame computes pivot ----
    __threadfence();
    __syncthreads();
    __shared__ int sh_last;
    __shared__ unsigned psum[256];
    if (threadIdx.x == 0)
        sh_last = (atomicAdd(&g_done[b], 1) == FBLK - 1) ? 1 : 0;
    __syncthreads();
    if (!sh_last) return;

    const int t = threadIdx.x;
    unsigned s = 0;
    {
        const uint4* HV = (const uint4*)(H + t * 64);
#pragma unroll
        for (int i = 0; i < 16; ++i) { uint4 v = HV[i]; s += v.x + v.y + v.z + v.w; }
    }
    psum[t] = s;
    __syncthreads();
    for (int off = 1; off < 256; off <<= 1) {
        unsigned add = (t >= off) ? psum[t - off] : 0u;
        __syncthreads();
        psum[t] += add;
        __syncthreads();
    }
    unsigned incl = psum[t];
    unsigned excl = incl - s;
    if (excl < PRE && incl >= PRE) {
        unsigned c = excl;
        int p = t * 64;
        while (c + H[p] < PRE) { c += H[p]; ++p; }
        g_thresh[b] = p;
    }
    __syncthreads();   // walker done before anyone zeroes
    {
        uint4* HV = (uint4*)(H + t * 64);
#pragma unroll
        for (int i = 0; i < 16; ++i) HV[i] = make_uint4(0, 0, 0, 0);
    }
    if (t == 0) { g_cnt[b] = 0; g_done[b] = 0; }
}

// ---------------------------------------------------------------------------
// K2: chip-wide compaction with warp-aggregated counter atomics.
// ---------------------------------------------------------------------------
__global__ __launch_bounds__(256) void k_compact() {
    const int b = blockIdx.y;
    const int q = blockIdx.x * 256 + threadIdx.x;
    const bool valid = (q < QAn);
    const unsigned th = (unsigned)g_thresh[b];

    float4 s4 = valid ? ((const float4*)g_maxs)[b * QAn + q]
                      : make_float4(-1.f, -1.f, -1.f, -1.f);   // bin(2.0)=16384 > th
    float sv[4] = {s4.x, s4.y, s4.z, s4.w};
#pragma unroll
    for (int l = 0; l < 4; ++l) {
        bool take = (score_bin(sv[l]) <= th);
        unsigned bal = __ballot_sync(0xFFFFFFFFu, take);
        if (take) {
            int lane = (int)(threadIdx.x & 31);
            int leader = __ffs(bal) - 1;
            int base;
            if (lane == leader) base = atomicAdd(&g_cnt[b], __popc(bal));
            base = __shfl_sync(bal, base, leader);
            int pos = base + __popc(bal & ((1u << lane) - 1u));
            if (pos < CAP) {
                int a = q * 4 + l;
                g_cand[b * CAP + pos] =
                    ((unsigned long long)__float_as_uint(sv[l]) << 32) | (unsigned)(~a);
            }
        }
    }
}

// ---------------------------------------------------------------------------
// K3: per-frame — sort candidates (exact top-750 order), NMS, fused gather.
// ---------------------------------------------------------------------------
__global__ __launch_bounds__(1024) void k_select(const float* __restrict__ raw,
                                                 const float* __restrict__ vid,
                                                 const float* __restrict__ reg,
                                                 float* __restrict__ out) {
    const int b = blockIdx.x;
    const int tid = threadIdx.x;
    const int T = 1024;

    __shared__ unsigned long long keys[1024];
    __shared__ float bx1[PRE], by1[PRE], bx2[PRE], by2[PRE], barea[PRE];
    __shared__ int bcls[PRE];
    __shared__ int keep[PRE];
    __shared__ unsigned pairs[1024];
    __shared__ int sh_final[POST];
    __shared__ unsigned hist[256];
    __shared__ unsigned long long sh_prefix;
    __shared__ unsigned sh_k;
    __shared__ int sh_pos, sh_maxbits, sh_np, sh_kept, sh_fallback;

    const float* ms = g_maxs + (size_t)b * An;
    const int* cl = g_cls + (size_t)b * An;

    int cnt = g_cnt[b];

    if (cnt <= CAP) {
        keys[tid] = (tid < cnt) ? g_cand[b * CAP + tid] : 0ULL;
    } else {
        // exact fallback (provably ~never): 8-pass 64-bit radix select over ms
        unsigned long long prefix = 0ULL;
        unsigned kk = PRE;
        const int ITER = (An + T - 1) / T;
        for (int pass = 0; pass < 8; ++pass) {
            int shift = 56 - pass * 8;
            unsigned long long hi_mask = (pass == 0) ? 0ULL : (~0ULL << (unsigned)(shift + 8));
            for (int i = tid; i < 256; i += T) hist[i] = 0;
            __syncthreads();
            for (int it = 0; it < ITER; ++it) {
                int a = it * T + tid;
                if (a < An) {
                    unsigned long long key =
                        ((unsigned long long)__float_as_uint(ms[a]) << 32) | (unsigned)(~a);
                    if ((key & hi_mask) == prefix)
                        atomicAdd(&hist[(unsigned)(key >> shift) & 255u], 1u);
                }
            }
            __syncthreads();
            if (tid == 0) {
                unsigned cum = 0; int d = 255;
                for (; d >= 0; --d) {
                    unsigned c = hist[d];
                    if (cum + c >= kk) break;
                    cum += c;
                }
                if (d < 0) d = 0;
                prefix |= ((unsigned long long)d) << shift;
                kk -= cum;
                sh_prefix = prefix; sh_k = kk;
            }
            __syncthreads();
            prefix = sh_prefix; kk = sh_k;
            __syncthreads();
        }
        if (tid == 0) sh_pos = 0;
        __syncthreads();
        for (int a = tid; a < An; a += T) {
            unsigned long long key =
                ((unsigned long long)__float_as_uint(ms[a]) << 32) | (unsigned)(~a);
            if (key >= prefix) {
                int pos = atomicAdd(&sh_pos, 1);
                if (pos < 1024) keys[pos] = key;
            }
        }
        __syncthreads();
        int c2 = sh_pos; if (c2 > 1024) c2 = 1024;
        for (int i = c2 + tid; i < 1024; i += T) keys[i] = 0ULL;
    }
    __syncthreads();

    // ---- hybrid bitonic sort, descending by true key ----
    {
        unsigned long long v = keys[tid];
        for (int k2 = 2; k2 <= 1024; k2 <<= 1) {
            bool dirmax = ((tid & k2) == 0);
            for (int j = k2 >> 1; j >= 1; j >>= 1) {
                unsigned long long o;
                if (j >= 32) {
                    keys[tid] = v;
                    __syncthreads();
                    o = keys[tid ^ j];
                    __syncthreads();
                } else {
                    o = __shfl_xor_sync(0xFFFFFFFFu, v, j);
                }
                bool lower = ((tid & j) == 0);
                bool takeMax = (lower == dirmax);
                bool gt = (v > o);
                v = (takeMax == gt) ? v : o;
            }
        }
        keys[tid] = v;
        __syncthreads();
    }

    // ---- boxes/classes for sorted top-750; max coordinate ----
    if (tid == 0) { sh_maxbits = 0; sh_fallback = 0; }
    __syncthreads();
    if (tid < PRE) {
        int i = tid;
        int a = (int)(~(unsigned)(keys[i] & 0xFFFFFFFFULL));
        const float* rb = raw + (size_t)b * 84 * An;
        float x1 = rb[0 * (size_t)An + a];
        float y1 = rb[1 * (size_t)An + a];
        float x2 = rb[2 * (size_t)An + a];
        float y2 = rb[3 * (size_t)An + a];
        bx1[i] = x1; by1[i] = y1; bx2[i] = x2; by2[i] = y2;
        bcls[i] = cl[a];
        float m = fmaxf(fmaxf(x1, y1), fmaxf(x2, y2));
        atomicMax(&sh_maxbits, __float_as_int(m));
    }
    __syncthreads();

    float off_scale = __int_as_float(sh_maxbits) + 1.0f;
    if (tid < PRE) {
        int i = tid;
        float off = (float)bcls[i] * off_scale;
        float x1 = bx1[i] + off, y1 = by1[i] + off;
        float x2 = bx2[i] + off, y2 = by2[i] + off;
        bx1[i] = x1; by1[i] = y1; bx2[i] = x2; by2[i] = y2;
        barea[i] = (x2 - x1) * (y2 - y1);
    }
    __syncthreads();

    // ---- NMS: windowed conflict pairs + serial resolve ----
    {
        int W = 64;
        for (;;) {
            if (tid == 0) sh_np = 0;
            if (tid < PRE) keep[tid] = 1;
            __syncthreads();

            for (int p = tid; p < W * PRE; p += T) {
                int i = p / PRE;
                int j = p - i * PRE;
                if (j > i && bcls[i] == bcls[j]) {
                    float iw = fmaxf(fminf(bx2[i], bx2[j]) - fmaxf(bx1[i], bx1[j]), 0.0f);
                    float ih = fmaxf(fminf(by2[i], by2[j]) - fmaxf(by1[i], by1[j]), 0.0f);
                    float inter = iw * ih;
                    float iou = __fdiv_rn(inter, barea[i] + barea[j] - inter);
                    if (iou > 0.4f) {
                        int k = atomicAdd(&sh_np, 1);
                        if (k < 1024) pairs[k] = ((unsigned)i << 10) | (unsigned)j;
                    }
                }
            }
            __syncthreads();
            int np = sh_np;
            if (np > 1024) { if (tid == 0) sh_fallback = 1; __syncthreads(); break; }

            if (tid == 0) {
                for (int a2 = 1; a2 < np; ++a2) {
                    unsigned v = pairs[a2];
                    int b2 = a2 - 1;
                    while (b2 >= 0 && pairs[b2] > v) { pairs[b2 + 1] = pairs[b2]; --b2; }
                    pairs[b2 + 1] = v;
                }
                for (int p2 = 0; p2 < np; ++p2) {
                    unsigned v = pairs[p2];
                    int i = (int)(v >> 10), j = (int)(v & 1023u);
                    if (keep[i]) keep[j] = 0;
                }
                int kept = 0;
                for (int i = 0; i < W && kept < POST; ++i) kept += keep[i];
                sh_kept = kept;
            }
            __syncthreads();
            if (sh_kept >= POST || W >= PRE) break;
            W = (W * 4 < PRE) ? W * 4 : PRE;
            __syncthreads();
        }
    }

    if (sh_fallback) {  // pathological conflict counts only
        if (tid < PRE) keep[tid] = 1;
        __syncthreads();
        int i = 0, kept = 0;
        while (i < PRE && kept < POST) {
            while (i < PRE && !keep[i]) ++i;
            if (i >= PRE) break;
            float X1 = bx1[i], Y1 = by1[i], X2 = bx2[i], Y2 = by2[i], AR = barea[i];
            int CI = bcls[i];
            for (int j = i + 1 + tid; j < PRE; j += T) {
                if (keep[j] && bcls[j] == CI) {
                    float iw = fmaxf(fminf(X2, bx2[j]) - fmaxf(X1, bx1[j]), 0.0f);
                    float ih = fmaxf(fminf(Y2, by2[j]) - fmaxf(Y1, by1[j]), 0.0f);
                    float inter = iw * ih;
                    float iou = __fdiv_rn(inter, AR + barea[j] - inter);
                    if (iou > 0.4f) keep[j] = 0;
                }
            }
            ++kept; ++i;
            __syncthreads();
        }
    }

    // ---- stable-partition: first 30 kept, then unkept fill ----
    if (tid == 0) {
        int c2 = 0;
        for (int i = 0; i < PRE && c2 < POST; ++i)
            if (keep[i]) sh_final[c2++] = i;
        for (int i = 0; i < PRE && c2 < POST; ++i)
            if (!keep[i]) sh_final[c2++] = i;
    }
    __syncthreads();

    // ---- fused gather ----
    for (int w2 = tid; w2 < POST * 128; w2 += T) {
        int c = w2 >> 7;
        int f = w2 & 127;
        int i = sh_final[c];
        int a = (int)(~(unsigned)(keys[i] & 0xFFFFFFFFULL));
        size_t r = (size_t)b * POST + c;
        size_t row = ((size_t)b * An + a) * CH;
        if (f < 64)
            ((float4*)(out + OUT_CLS_OFF))[r * 64 + f] = __ldg((const float4*)(vid + row) + f);
        else
            ((float4*)(out + OUT_REG_OFF))[r * 64 + (f - 64)] = __ldg((const float4*)(reg + row) + (f - 64));
    }
    if (tid < POST * 4) {
        int c = tid >> 2, d = tid & 3;
        int i = sh_final[c];
        int a = (int)(~(unsigned)(keys[i] & 0xFFFFFFFFULL));
        out[OUT_BOX_OFF + (b * POST + c) * 4 + d] = raw[(size_t)b * 84 * An + (size_t)d * An + a];
    }
    if (tid >= 128 && tid < 128 + POST) {
        int c = tid - 128;
        int i = sh_final[c];
        out[OUT_SC_OFF + b * POST + c] = __uint_as_float((unsigned)(keys[i] >> 32));
    }
}

// ---------------------------------------------------------------------------
extern "C" void kernel_launch(void* const* d_in, const int* in_sizes, int n_in,
                              void* d_out, int out_size) {
    const float* raw = (const float*)d_in[0];
    const float* vid = (const float*)d_in[1];
    const float* reg = (const float*)d_in[2];
    float* out = (float*)d_out;

    dim3 g(FBLK, Bn);
    k_maxscore<<<g, 256>>>(raw);
    k_compact<<<g, 256>>>();
    k_select<<<Bn, 1024>>>(raw, vid, reg, out);
}